// round 1
// baseline (speedup 1.0000x reference)
#include <cuda_runtime.h>
#include <cstdint>
#include <cstddef>

// Problem constants
#define TT   1024
#define BBATCH 512
#define II   32
#define HH   256
#define OO   32

#define NGRP 16        // batch groups (32 rows each)
#define GCTA 8         // CTAs per group (each owns 32 h-indices)
#define BT   32        // batch rows per group
#define JT   32        // h-indices per CTA
#define ROWS 128       // gate rows per CTA (4 gates x 32 h-idx)
#define KDIM 288       // H + I
#define KPAD 292       // padded stride: 292*4B = 73 x 16B chunks, 73 % 8 == 1 -> conflict-free
#define OUTSTRIDE 260  // padded W_out stride (65 x 16B chunks, % 8 == 1)

// Persistent state across the launch (scratch; no allocation allowed)
__device__ __align__(16) float    g_hbuf[2][BBATCH][HH];  // double-buffered hidden state
__device__ unsigned               g_bar[NGRP];            // per-group monotonic barrier counters

__global__ void init_kernel() {
    int idx = blockIdx.x * blockDim.x + threadIdx.x;
    if (idx < BBATCH * HH) ((float*)g_hbuf)[idx] = 0.0f;   // zero h^(0) (buffer parity 0)
    if (idx < NGRP) g_bar[idx] = 0u;
}

__device__ __forceinline__ void ffma2(unsigned long long& acc,
                                      unsigned long long a,
                                      unsigned long long b) {
    asm volatile("fma.rn.f32x2 %0, %1, %2, %0;" : "+l"(acc) : "l"(a), "l"(b));
}
__device__ __forceinline__ float unpack_sum(unsigned long long a) {
    float lo = __uint_as_float((unsigned)(a & 0xffffffffull));
    float hi = __uint_as_float((unsigned)(a >> 32));
    return lo + hi;
}
__device__ __forceinline__ unsigned ld_acquire_u32(const unsigned* p) {
    unsigned v;
    asm volatile("ld.acquire.gpu.u32 %0, [%1];" : "=r"(v) : "l"(p));
    return v;
}

__global__ void __launch_bounds__(128, 1)
lstm_kernel(const float* __restrict__ x, const float* __restrict__ phys,
            const float* __restrict__ Wih, const float* __restrict__ Whh,
            const float* __restrict__ bih, const float* __restrict__ bhh,
            const float* __restrict__ Wout, const float* __restrict__ bout,
            float* __restrict__ out) {
    extern __shared__ float smem[];
    float* w_s    = smem;                   // [ROWS][KPAD]  weights (resident all steps)
    float* hx_s   = w_s + ROWS * KPAD;      // [BT][KPAD]    h(t) ++ x(t) per batch row
    float* c_s    = hx_s + BT * KPAD;       // [BT][JT]      cell state (CTA-private)
    float* bias_s = c_s + BT * JT;          // [ROWS]        b_ih + b_hh
    float* wout_s = bias_s + ROWS;          // [4][OUTSTRIDE] W_out slice
    float* bout_s = wout_s + 4 * OUTSTRIDE; // [4]

    const int tid = threadIdx.x;
    const int cta = blockIdx.x;
    const int grp = cta >> 3;     // 0..15 (batch group)
    const int g8  = cta & 7;      // 0..7  (gate slice within group)
    const int b0  = grp * BT;     // batch base
    const int j0  = g8 * JT;      // h-index base

    // ---- one-time loads into smem ----
    for (int i = tid; i < ROWS * KDIM; i += 128) {
        int r = i / KDIM, k = i - r * KDIM;
        int q = r >> 5, jj = r & 31;
        int grow = q * HH + j0 + jj;                 // global gate-row (i,f,g,o major)
        float v = (k < HH) ? Whh[grow * HH + k] : Wih[grow * II + (k - HH)];
        w_s[r * KPAD + k] = v;
    }
    for (int r = tid; r < ROWS; r += 128) {
        int q = r >> 5, jj = r & 31;
        int grow = q * HH + j0 + jj;
        bias_s[r] = bih[grow] + bhh[grow];
    }
    for (int i = tid; i < 4 * HH; i += 128) {
        int o = i >> 8, k = i & 255;
        wout_s[o * OUTSTRIDE + k] = Wout[(g8 * 4 + o) * HH + k];
    }
    if (tid < 4) bout_s[tid] = bout[g8 * 4 + tid];
    for (int i = tid; i < BT * JT; i += 128) c_s[i] = 0.0f;
    __syncthreads();

    // thread tiling for the gate GEMM: lane j in 0..31 (h-index), bt in 0..3 (8-batch strip)
    const int j  = tid & 31;
    const int bt = tid >> 5;
    const float* wr0 = w_s + (j)      * KPAD;  // i-gate row
    const float* wr1 = w_s + (32 + j) * KPAD;  // f-gate row
    const float* wr2 = w_s + (64 + j) * KPAD;  // g-gate row
    const float* wr3 = w_s + (96 + j) * KPAD;  // o-gate row
    const float* hbase = hx_s + (bt * 8) * KPAD;

    // out-projection mapping: one (batch,outcol) per thread
    const int ob = tid >> 2;      // 0..31
    const int oo = tid & 3;       // 0..3

    for (int t = 0; t <= TT; ++t) {
        // ---- stage h(t) ++ x(t) into smem ----
        const float* hsrc = &g_hbuf[t & 1][b0][0];
        for (int i = tid; i < BT * 72; i += 128) {   // 72 float4 per row
            int b = i / 72, kc = i - b * 72;
            float4 v;
            if (kc < 64) {
                v = *(const float4*)(hsrc + b * HH + kc * 4);
            } else if (t < TT) {
                v = *(const float4*)(x + ((size_t)t * BBATCH + b0 + b) * II + (kc - 64) * 4);
            } else {
                v = make_float4(0.f, 0.f, 0.f, 0.f);
            }
            *(float4*)(hx_s + b * KPAD + kc * 4) = v;
        }
        __syncthreads();

        // ---- output projection for step t-1 (uses the h just staged) ----
        if (t > 0) {
            const float* hp = hx_s + ob * KPAD;
            const float* wp = wout_s + oo * OUTSTRIDE;
            float a0 = 0.f, a1 = 0.f, a2 = 0.f, a3 = 0.f;
#pragma unroll 8
            for (int k = 0; k < HH; k += 4) {
                float4 hv = *(const float4*)(hp + k);
                float4 wv = *(const float4*)(wp + k);
                a0 = fmaf(hv.x, wv.x, a0);
                a1 = fmaf(hv.y, wv.y, a1);
                a2 = fmaf(hv.z, wv.z, a2);
                a3 = fmaf(hv.w, wv.w, a3);
            }
            float rnn = (a0 + a1) + (a2 + a3) + bout_s[oo];
            int tm1 = t - 1;
            int bglob = b0 + ob;
            int ocol = g8 * 4 + oo;
            float ph = phys[((size_t)tm1 * BBATCH + bglob) * OO + ocol];
            size_t oidx = ((size_t)bglob * TT + tm1) * OO + ocol;
            out[oidx] = ph + rnn;                               // full_pred [B,T,O]
            out[(size_t)BBATCH * TT * OO + oidx] = rnn;         // rnn_pred  [B,T,O]
        }
        if (t == TT) break;

        // ---- gate GEMM: acc[q][bb] over K=288, packed f32x2 FMAs ----
        unsigned long long acc[4][8];
#pragma unroll
        for (int q = 0; q < 4; ++q)
#pragma unroll
            for (int bb = 0; bb < 8; ++bb) acc[q][bb] = 0ull;

#pragma unroll 2
        for (int k = 0; k < KDIM; k += 4) {
            ulonglong2 w0 = *(const ulonglong2*)(wr0 + k);
            ulonglong2 w1 = *(const ulonglong2*)(wr1 + k);
            ulonglong2 w2 = *(const ulonglong2*)(wr2 + k);
            ulonglong2 w3 = *(const ulonglong2*)(wr3 + k);
#pragma unroll
            for (int bb = 0; bb < 8; ++bb) {
                ulonglong2 hv = *(const ulonglong2*)(hbase + bb * KPAD + k);
                ffma2(acc[0][bb], hv.x, w0.x); ffma2(acc[0][bb], hv.y, w0.y);
                ffma2(acc[1][bb], hv.x, w1.x); ffma2(acc[1][bb], hv.y, w1.y);
                ffma2(acc[2][bb], hv.x, w2.x); ffma2(acc[2][bb], hv.y, w2.y);
                ffma2(acc[3][bb], hv.x, w3.x); ffma2(acc[3][bb], hv.y, w3.y);
            }
        }

        // ---- LSTM elementwise update (c is CTA/thread-private) ----
        float* hdst = &g_hbuf[(t + 1) & 1][b0][0];
#pragma unroll
        for (int bb = 0; bb < 8; ++bb) {
            int b = bt * 8 + bb;
            float gi = unpack_sum(acc[0][bb]) + bias_s[j];
            float gf = unpack_sum(acc[1][bb]) + bias_s[32 + j];
            float gg = unpack_sum(acc[2][bb]) + bias_s[64 + j];
            float go = unpack_sum(acc[3][bb]) + bias_s[96 + j];
            float ig = 1.0f / (1.0f + __expf(-gi));
            float fg = 1.0f / (1.0f + __expf(-gf));
            float gt = tanhf(gg);
            float og = 1.0f / (1.0f + __expf(-go));
            float cn = fg * c_s[b * JT + j] + ig * gt;
            float hn = og * tanhf(cn);
            c_s[b * JT + j] = cn;
            hdst[b * HH + j0 + j] = hn;
        }

        // ---- group barrier (8 CTAs), monotonic counter ----
        __threadfence();
        __syncthreads();
        if (tid == 0) {
            atomicAdd(&g_bar[grp], 1u);
            unsigned target = 8u * (unsigned)(t + 1);
            while (ld_acquire_u32(&g_bar[grp]) < target) { }
        }
        __syncthreads();
    }
}

extern "C" void kernel_launch(void* const* d_in, const int* in_sizes, int n_in,
                              void* d_out, int out_size) {
    const float* x    = (const float*)d_in[0];
    const float* phys = (const float*)d_in[1];
    const float* Wih  = (const float*)d_in[2];
    const float* Whh  = (const float*)d_in[3];
    const float* bih  = (const float*)d_in[4];
    const float* bhh  = (const float*)d_in[5];
    const float* Wout = (const float*)d_in[6];
    const float* bout = (const float*)d_in[7];
    float* out = (float*)d_out;

    size_t smem_bytes = (size_t)(ROWS * KPAD + BT * KPAD + BT * JT + ROWS +
                                 4 * OUTSTRIDE + 4) * sizeof(float);  // 195,664 B

    cudaFuncSetAttribute(lstm_kernel,
                         cudaFuncAttributeMaxDynamicSharedMemorySize,
                         (int)smem_bytes);

    init_kernel<<<(BBATCH * HH + 255) / 256, 256>>>();
    lstm_kernel<<<NGRP * GCTA, 128, smem_bytes>>>(x, phys, Wih, Whh, bih, bhh,
                                                  Wout, bout, out);
}

// round 2
// speedup vs baseline: 1.0645x; 1.0645x over previous
#include <cuda_runtime.h>
#include <cstdint>
#include <cstddef>

// Problem constants
#define TT   1024
#define BB   512
#define II   32
#define HH   256
#define OO   32
#define KDIM 288      // H + I

#define NGRP 16       // batch groups (32 rows each)
#define GCTA 8        // CTAs per group (each owns 32 j-indices)
#define BT   32       // batch rows per group (= lanes)
#define JT   32       // j-indices per CTA
#define NTHR 256      // 8 warps per CTA

#define WST   132     // w_t row stride (k-major): (4k+r)%32 conflict-free, 528B = 33*16 aligned
#define HXST  36      // hx row stride: (4k+b)%32 conflict-free, 144B 16-aligned
#define WOUTST 260

// Persistent scratch (no allocation allowed)
__device__ __align__(16) float    g_h[2][NGRP][HH][BT];   // transposed hidden state [par][grp][j][b]
__device__ unsigned               g_bar[NGRP];            // per-group monotonic barrier counters

__global__ void init_kernel() {
    int idx = blockIdx.x * blockDim.x + threadIdx.x;
    if (idx < NGRP * HH * BT) ((float*)g_h)[idx] = 0.0f;  // zero h^(0) (parity 0)
    if (idx < NGRP) g_bar[idx] = 0u;
}

typedef unsigned long long ull;

__device__ __forceinline__ void ffma2(ull& acc, ull a, ull b) {
    asm volatile("fma.rn.f32x2 %0, %1, %2, %0;" : "+l"(acc) : "l"(a), "l"(b));
}
__device__ __forceinline__ ull pack2(float a, float b) {
    ull r; asm("mov.b64 %0, {%1, %2};" : "=l"(r) : "f"(a), "f"(b)); return r;
}
__device__ __forceinline__ float2 unpack2(ull v) {
    float2 r; asm("mov.b64 {%0, %1}, %2;" : "=f"(r.x), "=f"(r.y) : "l"(v)); return r;
}
__device__ __forceinline__ unsigned ld_acquire_u32(const unsigned* p) {
    unsigned v;
    asm volatile("ld.acquire.gpu.u32 %0, [%1];" : "=r"(v) : "l"(p));
    return v;
}
__device__ __forceinline__ float sigf(float x) {
    return __fdividef(1.0f, 1.0f + __expf(-x));
}
__device__ __forceinline__ float tanh_fast(float x) {
    float ax = fabsf(x);
    float e  = __expf(-2.0f * ax);                 // e in (0,1], no overflow
    float r  = __fdividef(1.0f - e, 1.0f + e);
    return copysignf(r, x);
}

__global__ void __launch_bounds__(NTHR, 1)
lstm_kernel(const float* __restrict__ x, const float* __restrict__ phys,
            const float* __restrict__ Wih, const float* __restrict__ Whh,
            const float* __restrict__ bih, const float* __restrict__ bhh,
            const float* __restrict__ Wout, const float* __restrict__ bout,
            float* __restrict__ out) {
    extern __shared__ float smem[];
    float* w_s    = smem;                    // [KDIM][WST]   transposed weights, r = jj*4 + q
    float* hx     = w_s + KDIM * WST;        // [KDIM][HXST]  h(t) ++ x(t), transposed [k][b]
    float* wout_s = hx + KDIM * HXST;        // [4][WOUTST]
    float* bout_s = wout_s + 4 * WOUTST;     // [4]

    const int tid  = threadIdx.x;
    const int cta  = blockIdx.x;
    const int grp  = cta >> 3;               // batch group 0..15
    const int g8   = cta & 7;                // j-slice within group 0..7
    const int b0   = grp * BT;
    const int j0   = g8 * JT;
    const int w    = tid >> 5;               // warp 0..7 -> owns jj in [w*4, w*4+4)
    const int lane = tid & 31;               // lane = batch within group

    // ---- one-time: weights transposed into smem ----
    for (int i = tid; i < 128 * KDIM; i += NTHR) {
        int r = i / KDIM, k = i - r * KDIM;
        int q = r & 3, jj = r >> 2;
        int grow = q * HH + j0 + jj;
        float v = (k < HH) ? Whh[grow * HH + k] : Wih[grow * II + (k - HH)];
        w_s[k * WST + r] = v;
    }
    for (int i = tid; i < 4 * HH; i += NTHR) {
        int o = i >> 8, k = i & 255;
        wout_s[o * WOUTST + k] = Wout[(g8 * 4 + o) * HH + k];
    }
    if (tid < 4) bout_s[tid] = bout[g8 * 4 + tid];

    // biases pre-packed into accumulator-init registers
    ull bias01[4], bias23[4];
#pragma unroll
    for (int jt = 0; jt < 4; ++jt) {
        int gj = j0 + w * 4 + jt;
        bias01[jt] = pack2(bih[0 * HH + gj] + bhh[0 * HH + gj],
                           bih[1 * HH + gj] + bhh[1 * HH + gj]);
        bias23[jt] = pack2(bih[2 * HH + gj] + bhh[2 * HH + gj],
                           bih[3 * HH + gj] + bhh[3 * HH + gj]);
    }

    float c[4] = {0.f, 0.f, 0.f, 0.f};       // cell state in registers
    __syncthreads();

    for (int t = 0; t <= TT; ++t) {
        // ---- stage h(t) (transposed, coalesced both ends) ----
        const float* hsrc = &g_h[t & 1][grp][0][0];
#pragma unroll
        for (int i = tid; i < HH * BT / 4; i += NTHR) {      // 2048 float4
            float4 v = ((const float4*)hsrc)[i];
            int k = i >> 3, b4 = (i & 7) * 4;
            *(float4*)(hx + k * HXST + b4) = v;
        }
        // ---- stage x(t) ----
        if (t < TT) {
            int b = tid >> 3, k4 = (tid & 7) * 4;            // one float4 per thread
            float4 v = *(const float4*)(x + ((size_t)t * BB + b0 + b) * II + k4);
            hx[(HH + k4 + 0) * HXST + b] = v.x;
            hx[(HH + k4 + 1) * HXST + b] = v.y;
            hx[(HH + k4 + 2) * HXST + b] = v.z;
            hx[(HH + k4 + 3) * HXST + b] = v.w;
        }
        __syncthreads();

        // ---- output projection for step t-1 (h(t) just staged == h after step t-1) ----
        if (t > 0 && tid < 128) {
            int b = tid >> 2, o = tid & 3;
            const float* hp = hx + b;
            const float* wp = wout_s + o * WOUTST;
            float a0 = 0.f, a1 = 0.f, a2 = 0.f, a3 = 0.f;
#pragma unroll 16
            for (int jv = 0; jv < HH; jv += 4) {
                a0 = fmaf(hp[(jv + 0) * HXST], wp[jv + 0], a0);
                a1 = fmaf(hp[(jv + 1) * HXST], wp[jv + 1], a1);
                a2 = fmaf(hp[(jv + 2) * HXST], wp[jv + 2], a2);
                a3 = fmaf(hp[(jv + 3) * HXST], wp[jv + 3], a3);
            }
            float rnn = (a0 + a1) + (a2 + a3) + bout_s[o];
            int tm1 = t - 1, bg = b0 + b, oc = g8 * 4 + o;
            float ph = phys[((size_t)tm1 * BB + bg) * OO + oc];
            size_t oi = ((size_t)bg * TT + tm1) * OO + oc;
            out[oi] = ph + rnn;                               // full_pred [B,T,O]
            out[(size_t)BB * TT * OO + oi] = rnn;             // rnn_pred  [B,T,O]
        }
        if (t == TT) break;

        // ---- gate GEMM: lanes = batch, weights broadcast, bias pre-folded ----
        ull acc[4][2];
#pragma unroll
        for (int jt = 0; jt < 4; ++jt) { acc[jt][0] = bias01[jt]; acc[jt][1] = bias23[jt]; }

        const float* hcol  = hx + lane;
        const float* wbase = w_s + w * 16;
#pragma unroll 4
        for (int k = 0; k < KDIM; ++k) {
            float hk = hcol[k * HXST];
            ull h2 = pack2(hk, hk);
            const float* wk = wbase + k * WST;
            ulonglong2 w0 = *(const ulonglong2*)(wk);
            ulonglong2 w1 = *(const ulonglong2*)(wk + 4);
            ulonglong2 w2 = *(const ulonglong2*)(wk + 8);
            ulonglong2 w3 = *(const ulonglong2*)(wk + 12);
            ffma2(acc[0][0], h2, w0.x); ffma2(acc[0][1], h2, w0.y);
            ffma2(acc[1][0], h2, w1.x); ffma2(acc[1][1], h2, w1.y);
            ffma2(acc[2][0], h2, w2.x); ffma2(acc[2][1], h2, w2.y);
            ffma2(acc[3][0], h2, w3.x); ffma2(acc[3][1], h2, w3.y);
        }

        // ---- LSTM elementwise update, c in regs, h store coalesced ----
        float* hdst = &g_h[(t + 1) & 1][grp][0][0];
#pragma unroll
        for (int jt = 0; jt < 4; ++jt) {
            float2 a01 = unpack2(acc[jt][0]);   // (gi, gf)
            float2 a23 = unpack2(acc[jt][1]);   // (gg, go)
            float ig = sigf(a01.x);
            float fg = sigf(a01.y);
            float gt = tanh_fast(a23.x);
            float og = sigf(a23.y);
            float cn = fg * c[jt] + ig * gt;
            float hn = og * tanh_fast(cn);
            c[jt] = cn;
            hdst[(j0 + w * 4 + jt) * BT + lane] = hn;
        }

        // ---- group barrier (8 CTAs), monotonic counter ----
        __threadfence();
        __syncthreads();
        if (tid == 0) {
            atomicAdd(&g_bar[grp], 1u);
            unsigned target = 8u * (unsigned)(t + 1);
            while (ld_acquire_u32(&g_bar[grp]) < target) { }
        }
        __syncthreads();
    }
}

extern "C" void kernel_launch(void* const* d_in, const int* in_sizes, int n_in,
                              void* d_out, int out_size) {
    const float* x    = (const float*)d_in[0];
    const float* phys = (const float*)d_in[1];
    const float* Wih  = (const float*)d_in[2];
    const float* Whh  = (const float*)d_in[3];
    const float* bih  = (const float*)d_in[4];
    const float* bhh  = (const float*)d_in[5];
    const float* Wout = (const float*)d_in[6];
    const float* bout = (const float*)d_in[7];
    float* out = (float*)d_out;

    size_t smem_bytes = (size_t)(KDIM * WST + KDIM * HXST + 4 * WOUTST + 4) * sizeof(float);

    cudaFuncSetAttribute(lstm_kernel,
                         cudaFuncAttributeMaxDynamicSharedMemorySize,
                         (int)smem_bytes);

    init_kernel<<<(NGRP * HH * BT + 255) / 256, 256>>>();
    lstm_kernel<<<NGRP * GCTA, NTHR, smem_bytes>>>(x, phys, Wih, Whh, bih, bhh,
                                                   Wout, bout, out);
}